// round 4
// baseline (speedup 1.0000x reference)
#include <cuda_runtime.h>
#include <math.h>

// ---------------- problem constants ----------------
#define NG    64      // graphs
#define ATOMS 32      // atoms per graph
#define NN    2048    // total nodes
#define HID   128
#define FEAT  64
#define BINS  32      // dist one-hot bins
#define D0    106     // dense dims: 128 -> 106 -> 85 -> 64
#define D1    85
#define D2    64

// ---------------- scratch (device globals; no allocs allowed) ----------------
__device__ float g_emb[NG * HID];
__device__ float g_isl[NG];           // 1/sqrt(length[g])
__device__ float g_x[NN * HID];
__device__ float g_q[NN * HID];
__device__ float g_k[NN * HID];
__device__ float g_v[NN * HID];
__device__ float g_bias[NN];
__device__ float g_gate[NN];
__device__ float g_vals[NN * HID];

// =====================================================================
// Kernel 1: emb[g] = next_type[g] @ W_emb^T  (64x128), + graph lengths
// grid 64, block 128
// =====================================================================
__global__ __launch_bounds__(128, 1) void k_prep(
    const float* __restrict__ nt, const float* __restrict__ Wemb,
    const int* __restrict__ batch)
{
    __shared__ float4 s_nt[FEAT / 4];
    __shared__ float  s_part[4];
    int g = blockIdx.x, t = threadIdx.x;
    if (t < FEAT / 4) s_nt[t] = ((const float4*)(nt + g * FEAT))[t];
    __syncthreads();

    // emb row: thread t computes output channel t
    const float4* w4 = (const float4*)Wemb + t * (FEAT / 4);
    float acc = 0.f;
#pragma unroll
    for (int f = 0; f < FEAT / 4; ++f) {
        float4 w = w4[f], x = s_nt[f];
        acc = fmaf(w.x, x.x, acc); acc = fmaf(w.y, x.y, acc);
        acc = fmaf(w.z, x.z, acc); acc = fmaf(w.w, x.w, acc);
    }
    g_emb[g * HID + t] = acc;

    // length[g] = count(batch == g)  (segment_sum of ones)
    int cnt = 0;
    for (int i = t; i < NN; i += 128) cnt += (batch[i] == g);
    for (int o = 16; o; o >>= 1) cnt += __shfl_down_sync(~0u, cnt, o);
    if ((t & 31) == 0) s_part[t >> 5] = (float)cnt;
    __syncthreads();
    if (t == 0)
        g_isl[g] = rsqrtf(s_part[0] + s_part[1] + s_part[2] + s_part[3]);
}

// =====================================================================
// Kernel 2: x = h * emb[batch];  qkv = x@Wqkv^T + b;  bias, gate.
// 16 nodes per block, 128 threads, grid 128.
// W chunk (128x128) staged in smem with stride 132 (conflict-free f4 LDS).
// Thread t owns output channel t of each chunk, 16 node accumulators.
// =====================================================================
#define NB2 16
__global__ __launch_bounds__(128, 1) void k_qkv(
    const float* __restrict__ h, const int* __restrict__ batch,
    const float* __restrict__ Wqkv, const float* __restrict__ bqkv,
    const float* __restrict__ Wb, const float* __restrict__ bb,
    const float* __restrict__ Wg, const float* __restrict__ bg)
{
    extern __shared__ float sm[];
    float* Xs = sm;                 // 16 * 132
    float* Ws = sm + NB2 * 132;     // 128 * 132
    int t = threadIdx.x;
    int base = blockIdx.x * NB2;

    // build x (smem + global)
    for (int idx = t; idx < NB2 * HID; idx += 128) {
        int n = idx >> 7, c = idx & 127;
        int node = base + n;
        float xv = h[node * HID + c] * g_emb[batch[node] * HID + c];
        Xs[n * 132 + c] = xv;
        g_x[node * HID + c] = xv;
    }
    __syncthreads();

    // bias & gate: warp w handles nodes w, w+4, w+8, w+12
    {
        int w = t >> 5, l = t & 31;
#pragma unroll
        for (int r = 0; r < 4; ++r) {
            int n = w + 4 * r;
            float pb = 0.f, pg = 0.f;
#pragma unroll
            for (int m = 0; m < 4; ++m) {
                float xv = Xs[n * 132 + l + 32 * m];
                pb = fmaf(xv, Wb[l + 32 * m], pb);
                pg = fmaf(xv, Wg[l + 32 * m], pg);
            }
            for (int o = 16; o; o >>= 1) {
                pb += __shfl_down_sync(~0u, pb, o);
                pg += __shfl_down_sync(~0u, pg, o);
            }
            if (l == 0) {
                g_bias[base + n] = pb + bb[0];
                float z = pg + bg[0];
                g_gate[base + n] = 1.f / (1.f + __expf(-z));
            }
        }
    }

    for (int j = 0; j < 3; ++j) {
        __syncthreads();
        for (int idx = t; idx < HID * HID; idx += 128) {
            int r = idx >> 7, c = idx & 127;
            Ws[r * 132 + c] = Wqkv[(j * HID + r) * HID + c];
        }
        __syncthreads();

        float acc[NB2];
#pragma unroll
        for (int n = 0; n < NB2; ++n) acc[n] = 0.f;
        const float4* W4 = (const float4*)Ws + t * 33;
        const float4* X4 = (const float4*)Xs;
#pragma unroll 2
        for (int kk = 0; kk < 32; ++kk) {
            float4 w4 = W4[kk];
#pragma unroll
            for (int n = 0; n < NB2; ++n) {
                float4 x4 = X4[n * 33 + kk];
                acc[n] = fmaf(w4.x, x4.x, acc[n]);
                acc[n] = fmaf(w4.y, x4.y, acc[n]);
                acc[n] = fmaf(w4.z, x4.z, acc[n]);
                acc[n] = fmaf(w4.w, x4.w, acc[n]);
            }
        }
        float bias = bqkv[j * HID + t];
        float* op = (j == 0) ? g_q : (j == 1) ? g_k : g_v;
#pragma unroll
        for (int n = 0; n < NB2; ++n)
            op[(base + n) * HID + t] = acc[n] + bias;
    }
}

// =====================================================================
// Kernel 3: block-diagonal attention. grid 128 = 64 graphs x 2 halves,
// block 128. Each block: 16 query rows vs the graph's 32 keys.
// logits = (q.k)*isl + bias_i + SoftOneHot(dist).Wt + bt; softmax;
// vals = (attn@v)*gate + x
// =====================================================================
__global__ __launch_bounds__(128, 1) void k_attn(
    const float* __restrict__ pos, const float* __restrict__ Wt,
    const float* __restrict__ bt)
{
    __shared__ float Qs[16 * 132];
    __shared__ float Ks[32 * 132];
    __shared__ float Vs[32 * 132];
    __shared__ float Ls[16 * 33];
    __shared__ float4 posS[32];
    __shared__ float biasS[16], gateS[16], WtS[32];

    int t = threadIdx.x;
    int g = blockIdx.x >> 1;
    int half = blockIdx.x & 1;
    int row0 = g * ATOMS + half * 16;
    int col0 = g * ATOMS;

    for (int idx = t; idx < 16 * HID; idx += 128) {
        int n = idx >> 7, c = idx & 127;
        Qs[n * 132 + c] = g_q[(row0 + n) * HID + c];
    }
    for (int idx = t; idx < 32 * HID; idx += 128) {
        int n = idx >> 7, c = idx & 127;
        Ks[n * 132 + c] = g_k[(col0 + n) * HID + c];
        Vs[n * 132 + c] = g_v[(col0 + n) * HID + c];
    }
    if (t < 32) {
        posS[t] = make_float4(pos[(col0 + t) * 3], pos[(col0 + t) * 3 + 1],
                              pos[(col0 + t) * 3 + 2], 0.f);
        WtS[t] = Wt[t];
    }
    if (t < 16) { biasS[t] = g_bias[row0 + t]; gateS[t] = g_gate[row0 + t]; }
    __syncthreads();

    float isl = g_isl[g];
    float btv = bt[0];

    // 512 (i,j) pairs; 4 per thread
#pragma unroll
    for (int it = 0; it < 4; ++it) {
        int p = t + it * 128;
        int i = p >> 5, j = p & 31;
        const float4* Q4 = (const float4*)Qs + i * 33;
        const float4* K4 = (const float4*)Ks + j * 33;
        float acc = 0.f;
#pragma unroll 8
        for (int kk = 0; kk < 32; ++kk) {
            float4 q4 = Q4[kk], k4 = K4[kk];
            acc = fmaf(q4.x, k4.x, acc); acc = fmaf(q4.y, k4.y, acc);
            acc = fmaf(q4.z, k4.z, acc); acc = fmaf(q4.w, k4.w, acc);
        }
        float4 pi = posS[half * 16 + i];
        float4 pj = posS[j];
        float dx = pi.x - pj.x, dy = pi.y - pj.y, dz = pi.z - pj.z;
        float sq = dx * dx + dy * dy + dz * dz;
        float d = sqrtf(fmaxf(sq, 1e-12f));
        float tv = btv;
#pragma unroll
        for (int m = 0; m < BINS; ++m) {
            float c = (10.f / 31.f) * (float)m;
            float df = d - c;
            tv = fmaf(__expf(-10.f * df * df), WtS[m], tv);
        }
        Ls[i * 33 + j] = acc * isl + biasS[i] + tv;
    }
    __syncthreads();

    // softmax over 32 cols; warp w handles rows w, w+4, w+8, w+12
    {
        int w = t >> 5, l = t & 31;
#pragma unroll
        for (int r = 0; r < 4; ++r) {
            int i = w + 4 * r;
            float v = Ls[i * 33 + l];
            float m = v;
            for (int o = 16; o; o >>= 1) m = fmaxf(m, __shfl_xor_sync(~0u, m, o));
            float e = __expf(v - m);
            float s = e;
            for (int o = 16; o; o >>= 1) s += __shfl_xor_sync(~0u, s, o);
            Ls[i * 33 + l] = e / s;
        }
    }
    __syncthreads();

    // attn @ v, gate, residual. lane owns 4 channels (float4), 4 rows/thread.
    {
        int lane = t & 31;
        int iBase = t >> 5;
        float4 acc[4];
#pragma unroll
        for (int r = 0; r < 4; ++r) acc[r] = make_float4(0.f, 0.f, 0.f, 0.f);
        const float4* V4 = (const float4*)Vs;
#pragma unroll 4
        for (int j = 0; j < 32; ++j) {
            float4 v4 = V4[j * 33 + lane];
#pragma unroll
            for (int r = 0; r < 4; ++r) {
                float a = Ls[(iBase + 4 * r) * 33 + j];
                acc[r].x = fmaf(a, v4.x, acc[r].x);
                acc[r].y = fmaf(a, v4.y, acc[r].y);
                acc[r].z = fmaf(a, v4.z, acc[r].z);
                acc[r].w = fmaf(a, v4.w, acc[r].w);
            }
        }
#pragma unroll
        for (int r = 0; r < 4; ++r) {
            int i = iBase + 4 * r;
            int node = row0 + i;
            float gv = gateS[i];
            float4 x4 = ((const float4*)(g_x + node * HID))[lane];
            float4 o4;
            o4.x = fmaf(acc[r].x, gv, x4.x);
            o4.y = fmaf(acc[r].y, gv, x4.y);
            o4.z = fmaf(acc[r].z, gv, x4.z);
            o4.w = fmaf(acc[r].w, gv, x4.w);
            ((float4*)(g_vals + node * HID))[lane] = o4;
        }
    }
}

// =====================================================================
// Kernel 4: dense head 128->106->85->64 (SiLU between) + log_softmax.
// 16 nodes per block, 128 threads, grid 128. Thread t owns output chan t.
// Padded k-dims (108 / 88) with zeroed pads so float4 loops are exact.
// Smem strides 132/108/92 -> conflict-free float4 LDS across lanes.
// =====================================================================
#define NB4 16
__global__ __launch_bounds__(128, 1) void k_dense(
    const float* __restrict__ Wd0, const float* __restrict__ bd0,
    const float* __restrict__ Wd1, const float* __restrict__ bd1,
    const float* __restrict__ Wd2, const float* __restrict__ bd2,
    float* __restrict__ out)
{
    extern __shared__ float sm[];
    float* A  = sm;                       // 16*132 (vals, later reused for Y)
    float* B  = A + NB4 * 132;            // 16*108
    float* C  = B + NB4 * 108;            // 16*88
    float* Ws = C + NB4 * 88;             // up to 106*132
    int t = threadIdx.x;
    int base = blockIdx.x * NB4;

    for (int idx = t; idx < NB4 * HID; idx += 128) {
        int n = idx >> 7, c = idx & 127;
        A[n * 132 + c] = g_vals[(base + n) * HID + c];
    }
    for (int idx = t; idx < D0 * HID; idx += 128) {
        int r = idx >> 7, c = idx & 127;
        Ws[r * 132 + c] = Wd0[idx];
    }
    __syncthreads();

    // L0: 128 -> 106, SiLU
    if (t < D0) {
        float acc[NB4];
#pragma unroll
        for (int n = 0; n < NB4; ++n) acc[n] = 0.f;
        const float4* W4 = (const float4*)Ws + t * 33;
        const float4* A4 = (const float4*)A;
#pragma unroll 2
        for (int kk = 0; kk < 32; ++kk) {
            float4 w4 = W4[kk];
#pragma unroll
            for (int n = 0; n < NB4; ++n) {
                float4 x4 = A4[n * 33 + kk];
                acc[n] = fmaf(w4.x, x4.x, acc[n]);
                acc[n] = fmaf(w4.y, x4.y, acc[n]);
                acc[n] = fmaf(w4.z, x4.z, acc[n]);
                acc[n] = fmaf(w4.w, x4.w, acc[n]);
            }
        }
        float bias = bd0[t];
#pragma unroll
        for (int n = 0; n < NB4; ++n) {
            float z = acc[n] + bias;
            B[n * 108 + t] = z / (1.f + __expf(-z));   // silu
        }
    } else if (t < 108) {
#pragma unroll
        for (int n = 0; n < NB4; ++n) B[n * 108 + t] = 0.f;
    }
    __syncthreads();

    for (int idx = t; idx < D1 * 108; idx += 128) {
        int r = idx / 108, c = idx - r * 108;
        Ws[r * 108 + c] = (c < D0) ? Wd1[r * D0 + c] : 0.f;
    }
    __syncthreads();

    // L1: 106(->108) -> 85, SiLU
    if (t < D1) {
        float acc[NB4];
#pragma unroll
        for (int n = 0; n < NB4; ++n) acc[n] = 0.f;
        const float4* W4 = (const float4*)Ws + t * 27;
        const float4* B4 = (const float4*)B;
#pragma unroll 2
        for (int kk = 0; kk < 27; ++kk) {
            float4 w4 = W4[kk];
#pragma unroll
            for (int n = 0; n < NB4; ++n) {
                float4 x4 = B4[n * 27 + kk];
                acc[n] = fmaf(w4.x, x4.x, acc[n]);
                acc[n] = fmaf(w4.y, x4.y, acc[n]);
                acc[n] = fmaf(w4.z, x4.z, acc[n]);
                acc[n] = fmaf(w4.w, x4.w, acc[n]);
            }
        }
        float bias = bd1[t];
#pragma unroll
        for (int n = 0; n < NB4; ++n) {
            float z = acc[n] + bias;
            C[n * 88 + t] = z / (1.f + __expf(-z));
        }
    } else if (t < 88) {
#pragma unroll
        for (int n = 0; n < NB4; ++n) C[n * 88 + t] = 0.f;
    }
    __syncthreads();

    for (int idx = t; idx < D2 * 88; idx += 128) {
        int r = idx / 88, c = idx - r * 88;
        Ws[r * 92 + c] = (c < D1) ? Wd2[r * D1 + c] : 0.f;
    }
    __syncthreads();

    // L2: 85(->88) -> 64 (no activation), Y reuses A region
    float* Y = A;
    if (t < D2) {
        float acc[NB4];
#pragma unroll
        for (int n = 0; n < NB4; ++n) acc[n] = 0.f;
        const float4* W4 = (const float4*)Ws + t * 23;
        const float4* C4 = (const float4*)C;
#pragma unroll 2
        for (int kk = 0; kk < 22; ++kk) {
            float4 w4 = W4[kk];
#pragma unroll
            for (int n = 0; n < NB4; ++n) {
                float4 x4 = C4[n * 22 + kk];
                acc[n] = fmaf(w4.x, x4.x, acc[n]);
                acc[n] = fmaf(w4.y, x4.y, acc[n]);
                acc[n] = fmaf(w4.z, x4.z, acc[n]);
                acc[n] = fmaf(w4.w, x4.w, acc[n]);
            }
        }
        float bias = bd2[t];
#pragma unroll
        for (int n = 0; n < NB4; ++n) Y[n * 64 + t] = acc[n] + bias;
    }
    __syncthreads();

    // log_softmax over 64; warp w handles nodes w, w+4, w+8, w+12
    {
        int w = t >> 5, l = t & 31;
#pragma unroll
        for (int r = 0; r < 4; ++r) {
            int n = w + 4 * r;
            float v0 = Y[n * 64 + l], v1 = Y[n * 64 + l + 32];
            float m = fmaxf(v0, v1);
            for (int o = 16; o; o >>= 1) m = fmaxf(m, __shfl_xor_sync(~0u, m, o));
            float s = __expf(v0 - m) + __expf(v1 - m);
            for (int o = 16; o; o >>= 1) s += __shfl_xor_sync(~0u, s, o);
            float ls = m + __logf(s);
            int node = base + n;
            out[node * 64 + l]      = v0 - ls;
            out[node * 64 + l + 32] = v1 - ls;
        }
    }
}

// =====================================================================
extern "C" void kernel_launch(void* const* d_in, const int* in_sizes, int n_in,
                              void* d_out, int out_size)
{
    const float* h     = (const float*)d_in[0];
    const float* pos   = (const float*)d_in[1];
    const float* nt    = (const float*)d_in[2];
    const int*   batch = (const int*)  d_in[3];
    const float* Wemb  = (const float*)d_in[4];
    const float* Wqkv  = (const float*)d_in[5];
    const float* bqkv  = (const float*)d_in[6];
    const float* Wb    = (const float*)d_in[7];
    const float* bb    = (const float*)d_in[8];
    const float* Wg    = (const float*)d_in[9];
    const float* bg    = (const float*)d_in[10];
    const float* Wt    = (const float*)d_in[11];
    const float* bt    = (const float*)d_in[12];
    const float* Wd0   = (const float*)d_in[13];
    const float* bd0   = (const float*)d_in[14];
    const float* Wd1   = (const float*)d_in[15];
    const float* bd1   = (const float*)d_in[16];
    const float* Wd2   = (const float*)d_in[17];
    const float* bd2   = (const float*)d_in[18];
    float* out = (float*)d_out;

    const int smem2 = (NB2 * 132 + 128 * 132) * 4;                       // 76032
    const int smem4 = (NB4 * 132 + NB4 * 108 + NB4 * 88 + D0 * 132) * 4; // 76960
    cudaFuncSetAttribute(k_qkv,   cudaFuncAttributeMaxDynamicSharedMemorySize, smem2);
    cudaFuncSetAttribute(k_dense, cudaFuncAttributeMaxDynamicSharedMemorySize, smem4);

    k_prep <<<NG, 128>>>(nt, Wemb, batch);
    k_qkv  <<<NN / NB2, 128, smem2>>>(h, batch, Wqkv, bqkv, Wb, bb, Wg, bg);
    k_attn <<<NG * 2, 128>>>(pos, Wt, bt);
    k_dense<<<NN / NB4, 128, smem4>>>(Wd0, bd0, Wd1, bd1, Wd2, bd2, out);
}

// round 6
// speedup vs baseline: 1.6120x; 1.6120x over previous
#include <cuda_runtime.h>
#include <math.h>

// ---------------- problem constants ----------------
#define NG    64      // graphs
#define ATOMS 32      // atoms per graph
#define NN    2048    // total nodes
#define HID   128
#define FEAT  64
#define BINS  32      // dist one-hot bins
#define D0    106     // dense dims: 128 -> 106 -> 85 -> 64
#define D1    85
#define D2    64

// ---------------- scratch (device globals; no allocs allowed) ----------------
__device__ float g_emb[NG * HID];
__device__ float g_isl[NG];           // 1/sqrt(length[g])
__device__ float g_x[NN * HID];
__device__ float g_q[NN * HID];
__device__ float g_k[NN * HID];
__device__ float g_v[NN * HID];
__device__ float g_bias[NN];
__device__ float g_gate[NN];
__device__ float g_vals[NN * HID];

// =====================================================================
// Kernel 1: emb[g] = next_type[g] @ W_emb^T (64x128) + graph lengths
// grid 64, block 128 (tiny)
// =====================================================================
__global__ __launch_bounds__(128, 1) void k_prep(
    const float* __restrict__ nt, const float* __restrict__ Wemb,
    const int* __restrict__ batch)
{
    __shared__ float4 s_nt[FEAT / 4];
    __shared__ float  s_part[4];
    int g = blockIdx.x, t = threadIdx.x;
    if (t < FEAT / 4) s_nt[t] = ((const float4*)(nt + g * FEAT))[t];
    __syncthreads();

    const float4* w4 = (const float4*)Wemb + t * (FEAT / 4);
    float acc = 0.f;
#pragma unroll
    for (int f = 0; f < FEAT / 4; ++f) {
        float4 w = w4[f], x = s_nt[f];
        acc = fmaf(w.x, x.x, acc); acc = fmaf(w.y, x.y, acc);
        acc = fmaf(w.z, x.z, acc); acc = fmaf(w.w, x.w, acc);
    }
    g_emb[g * HID + t] = acc;

    int cnt = 0;
    for (int i = t; i < NN; i += 128) cnt += (batch[i] == g);
    for (int o = 16; o; o >>= 1) cnt += __shfl_down_sync(~0u, cnt, o);
    if ((t & 31) == 0) s_part[t >> 5] = (float)cnt;
    __syncthreads();
    if (t == 0)
        g_isl[g] = rsqrtf(s_part[0] + s_part[1] + s_part[2] + s_part[3]);
}

// =====================================================================
// Kernel 2: x = h*emb[batch]; qkv = x@Wqkv^T + b; bias, gate.
// grid 128 (16 nodes/block), block 512: thread = (channel ch=t&127,
// node-quarter qq=t>>7). 16 warps/block -> 4 warps/SMSP.
// =====================================================================
__global__ __launch_bounds__(512, 1) void k_qkv(
    const float* __restrict__ h, const int* __restrict__ batch,
    const float* __restrict__ Wqkv, const float* __restrict__ bqkv,
    const float* __restrict__ Wb, const float* __restrict__ bb,
    const float* __restrict__ Wg, const float* __restrict__ bg)
{
    extern __shared__ float sm[];
    float*  Xs  = sm;                 // 16 * 132
    float*  Ws  = sm + 16 * 132;      // 128 * 132
    float4* Xs4 = (float4*)Xs;
    float4* Ws4 = (float4*)Ws;
    unsigned t = threadIdx.x;
    unsigned ch = t & 127u, qq = t >> 7;
    int base = blockIdx.x * 16;

    // build x: 512 float4s, exactly one per thread
    {
        unsigned n = t >> 5, c4 = t & 31u;
        int node = base + n;
        float4 hv = ((const float4*)(h + node * HID))[c4];
        float4 ev = ((const float4*)(g_emb + batch[node] * HID))[c4];
        float4 xv = make_float4(hv.x * ev.x, hv.y * ev.y, hv.z * ev.z, hv.w * ev.w);
        Xs4[n * 33 + c4] = xv;
        ((float4*)(g_x + node * HID))[c4] = xv;
    }
    __syncthreads();

    // bias & gate: 16 warps, warp w handles node w
    {
        unsigned w = t >> 5, l = t & 31u;
        float pb = 0.f, pg = 0.f;
#pragma unroll
        for (int m = 0; m < 4; ++m) {
            float xv = Xs[w * 132 + l + 32 * m];
            pb = fmaf(xv, Wb[l + 32 * m], pb);
            pg = fmaf(xv, Wg[l + 32 * m], pg);
        }
        for (int o = 16; o; o >>= 1) {
            pb += __shfl_down_sync(~0u, pb, o);
            pg += __shfl_down_sync(~0u, pg, o);
        }
        if (l == 0) {
            g_bias[base + w] = pb + bb[0];
            float z = pg + bg[0];
            g_gate[base + w] = 1.f / (1.f + __expf(-z));
        }
    }

#pragma unroll 1
    for (int j = 0; j < 3; ++j) {
        __syncthreads();
        const float4* Wg4 = (const float4*)(Wqkv + j * HID * HID);
#pragma unroll
        for (int i = 0; i < 8; ++i) {
            unsigned idx = t + i * 512;
            Ws4[(idx >> 5) * 33 + (idx & 31u)] = Wg4[idx];
        }
        __syncthreads();

        float acc0 = 0.f, acc1 = 0.f, acc2 = 0.f, acc3 = 0.f;
        const float4* W4 = Ws4 + ch * 33;
        const float4* X4 = Xs4 + (qq * 4) * 33;
#pragma unroll 4
        for (int kk = 0; kk < 32; ++kk) {
            float4 w4 = W4[kk];
            float4 a = X4[kk], b = X4[33 + kk], c = X4[66 + kk], d = X4[99 + kk];
            acc0 = fmaf(w4.x, a.x, acc0); acc0 = fmaf(w4.y, a.y, acc0);
            acc0 = fmaf(w4.z, a.z, acc0); acc0 = fmaf(w4.w, a.w, acc0);
            acc1 = fmaf(w4.x, b.x, acc1); acc1 = fmaf(w4.y, b.y, acc1);
            acc1 = fmaf(w4.z, b.z, acc1); acc1 = fmaf(w4.w, b.w, acc1);
            acc2 = fmaf(w4.x, c.x, acc2); acc2 = fmaf(w4.y, c.y, acc2);
            acc2 = fmaf(w4.z, c.z, acc2); acc2 = fmaf(w4.w, c.w, acc2);
            acc3 = fmaf(w4.x, d.x, acc3); acc3 = fmaf(w4.y, d.y, acc3);
            acc3 = fmaf(w4.z, d.z, acc3); acc3 = fmaf(w4.w, d.w, acc3);
        }
        float bias = bqkv[j * HID + ch];
        float* op = (j == 0) ? g_q : (j == 1) ? g_k : g_v;
        int r = base + qq * 4;
        op[(r + 0) * HID + ch] = acc0 + bias;
        op[(r + 1) * HID + ch] = acc1 + bias;
        op[(r + 2) * HID + ch] = acc2 + bias;
        op[(r + 3) * HID + ch] = acc3 + bias;
    }
}

// =====================================================================
// Kernel 3: block-diagonal attention. grid 128 = 64 graphs x 2 halves,
// block 512. 16 query rows vs graph's 32 keys.
// =====================================================================
__global__ __launch_bounds__(512, 1) void k_attn(
    const float* __restrict__ pos, const float* __restrict__ Wt,
    const float* __restrict__ bt)
{
    __shared__ float Qs[16 * 132];
    __shared__ float Ks[32 * 132];
    __shared__ float Vs[32 * 132];
    __shared__ float Ls[16 * 33];
    __shared__ float4 posS[32];
    __shared__ float biasS[16], gateS[16], WtS[32];

    unsigned t = threadIdx.x;
    int g = blockIdx.x >> 1;
    int half = blockIdx.x & 1;
    int row0 = g * ATOMS + half * 16;
    int col0 = g * ATOMS;

    float4* Qs4 = (float4*)Qs;
    float4* Ks4 = (float4*)Ks;
    float4* Vs4 = (float4*)Vs;

    // stage Q (512 f4, 1/thread), K+V (1024 f4 each, 2/thread each)
    {
        unsigned n = t >> 5, c4 = t & 31u;
        Qs4[n * 33 + c4] = ((const float4*)(g_q + (row0 + n) * HID))[c4];
#pragma unroll
        for (int i = 0; i < 2; ++i) {
            unsigned idx = t + i * 512;
            unsigned kn = idx >> 5, kc = idx & 31u;
            Ks4[kn * 33 + kc] = ((const float4*)(g_k + (col0 + kn) * HID))[kc];
            Vs4[kn * 33 + kc] = ((const float4*)(g_v + (col0 + kn) * HID))[kc];
        }
    }
    if (t < 32) {
        posS[t] = make_float4(pos[(col0 + t) * 3], pos[(col0 + t) * 3 + 1],
                              pos[(col0 + t) * 3 + 2], 0.f);
        WtS[t] = Wt[t];
    }
    if (t < 16) { biasS[t] = g_bias[row0 + t]; gateS[t] = g_gate[row0 + t]; }
    __syncthreads();

    float isl = g_isl[g];
    float btv = bt[0];

    // logits: 512 pairs, one per thread
    {
        unsigned i = t >> 5, j = t & 31u;
        const float4* Q4 = Qs4 + i * 33;   // broadcast within warp
        const float4* K4 = Ks4 + j * 33;   // stride-33 f4, conflict-free
        float acc = 0.f;
#pragma unroll 8
        for (int kk = 0; kk < 32; ++kk) {
            float4 q4 = Q4[kk], k4 = K4[kk];
            acc = fmaf(q4.x, k4.x, acc); acc = fmaf(q4.y, k4.y, acc);
            acc = fmaf(q4.z, k4.z, acc); acc = fmaf(q4.w, k4.w, acc);
        }
        float4 pi = posS[half * 16 + i];
        float4 pj = posS[j];
        float dx = pi.x - pj.x, dy = pi.y - pj.y, dz = pi.z - pj.z;
        float d = sqrtf(fmaxf(dx * dx + dy * dy + dz * dz, 1e-12f));
        // windowed SoftOneHot: only ~10 bins matter (exp(-10*(5*step)^2)~5e-12)
        const float step = 10.f / 31.f;
        int m0 = (int)(d * (31.f / 10.f)) - 4;
        m0 = max(0, min(BINS - 10, m0));
        float tv = btv;
#pragma unroll
        for (int m = 0; m < 10; ++m) {
            float c = step * (float)(m0 + m);
            float df = d - c;
            tv = fmaf(__expf(-10.f * df * df), WtS[m0 + m], tv);
        }
        Ls[i * 33 + j] = acc * isl + biasS[i] + tv;
    }
    __syncthreads();

    // softmax: warp w handles row w (16 warps, 16 rows)
    {
        unsigned w = t >> 5, l = t & 31u;
        float v = Ls[w * 33 + l];
        float m = v;
        for (int o = 16; o; o >>= 1) m = fmaxf(m, __shfl_xor_sync(~0u, m, o));
        float e = __expf(v - m);
        float s = e;
        for (int o = 16; o; o >>= 1) s += __shfl_xor_sync(~0u, s, o);
        Ls[w * 33 + l] = e / s;
    }
    __syncthreads();

    // attn@v + gate + residual: warp w owns row w, lane = f4 channel
    {
        unsigned w = t >> 5, lane = t & 31u;
        float4 acc = make_float4(0.f, 0.f, 0.f, 0.f);
#pragma unroll 8
        for (int j = 0; j < 32; ++j) {
            float a = Ls[w * 33 + j];             // broadcast
            float4 v4 = Vs4[j * 33 + lane];       // conflict-free
            acc.x = fmaf(a, v4.x, acc.x);
            acc.y = fmaf(a, v4.y, acc.y);
            acc.z = fmaf(a, v4.z, acc.z);
            acc.w = fmaf(a, v4.w, acc.w);
        }
        int node = row0 + w;
        float gv = gateS[w];
        float4 x4 = ((const float4*)(g_x + node * HID))[lane];
        float4 o4;
        o4.x = fmaf(acc.x, gv, x4.x);
        o4.y = fmaf(acc.y, gv, x4.y);
        o4.z = fmaf(acc.z, gv, x4.z);
        o4.w = fmaf(acc.w, gv, x4.w);
        ((float4*)(g_vals + node * HID))[lane] = o4;
    }
}

// =====================================================================
// Kernel 4: dense head 128->106->85->64 (SiLU between) + log_softmax.
// grid 128 (16 nodes), block 512: thread = (channel, node-quarter).
// =====================================================================
__global__ __launch_bounds__(512, 1) void k_dense(
    const float* __restrict__ Wd0, const float* __restrict__ bd0,
    const float* __restrict__ Wd1, const float* __restrict__ bd1,
    const float* __restrict__ Wd2, const float* __restrict__ bd2,
    float* __restrict__ out)
{
    extern __shared__ float sm[];
    float* A  = sm;                       // 16*132 (vals, reused for Y)
    float* B  = A + 16 * 132;             // 16*108
    float* C  = B + 16 * 108;             // 16*88
    float* Ws = C + 16 * 88;              // up to 106*132
    float4* A4s = (float4*)A;
    float4* W4s = (float4*)Ws;
    unsigned t = threadIdx.x;
    unsigned ch = t & 127u, qq = t >> 7;
    int base = blockIdx.x * 16;

    // stage vals (512 f4, 1/thread) and Wd0 (3392 f4)
    {
        unsigned n = t >> 5, c4 = t & 31u;
        A4s[n * 33 + c4] = ((const float4*)(g_vals + (base + n) * HID))[c4];
    }
    for (unsigned i = t; i < (unsigned)(D0 * 32); i += 512)
        W4s[(i >> 5) * 33 + (i & 31u)] = ((const float4*)Wd0)[i];
    __syncthreads();

    // ---- L0: 128 -> 106, SiLU ----
    if (ch < D0) {
        float acc0 = 0.f, acc1 = 0.f, acc2 = 0.f, acc3 = 0.f;
        const float4* W4 = W4s + ch * 33;
        const float4* X4 = A4s + (qq * 4) * 33;
#pragma unroll 4
        for (int kk = 0; kk < 32; ++kk) {
            float4 w4 = W4[kk];
            float4 a = X4[kk], b = X4[33 + kk], c = X4[66 + kk], d = X4[99 + kk];
            acc0 = fmaf(w4.x, a.x, acc0); acc0 = fmaf(w4.y, a.y, acc0);
            acc0 = fmaf(w4.z, a.z, acc0); acc0 = fmaf(w4.w, a.w, acc0);
            acc1 = fmaf(w4.x, b.x, acc1); acc1 = fmaf(w4.y, b.y, acc1);
            acc1 = fmaf(w4.z, b.z, acc1); acc1 = fmaf(w4.w, b.w, acc1);
            acc2 = fmaf(w4.x, c.x, acc2); acc2 = fmaf(w4.y, c.y, acc2);
            acc2 = fmaf(w4.z, c.z, acc2); acc2 = fmaf(w4.w, c.w, acc2);
            acc3 = fmaf(w4.x, d.x, acc3); acc3 = fmaf(w4.y, d.y, acc3);
            acc3 = fmaf(w4.z, d.z, acc3); acc3 = fmaf(w4.w, d.w, acc3);
        }
        float bias = bd0[ch];
        int nb = qq * 4;
        float z0 = acc0 + bias, z1 = acc1 + bias, z2 = acc2 + bias, z3 = acc3 + bias;
        B[(nb + 0) * 108 + ch] = z0 / (1.f + __expf(-z0));
        B[(nb + 1) * 108 + ch] = z1 / (1.f + __expf(-z1));
        B[(nb + 2) * 108 + ch] = z2 / (1.f + __expf(-z2));
        B[(nb + 3) * 108 + ch] = z3 / (1.f + __expf(-z3));
    } else if (ch < 108) {
        int nb = qq * 4;
#pragma unroll
        for (int n = 0; n < 4; ++n) B[(nb + n) * 108 + ch] = 0.f;
    }
    __syncthreads();

    for (unsigned idx = t; idx < (unsigned)(D1 * 108); idx += 512) {
        unsigned r = idx / 108u, c = idx - r * 108u;
        Ws[r * 108 + c] = (c < D0) ? Wd1[r * D0 + c] : 0.f;
    }
    __syncthreads();

    // ---- L1: 106(->108) -> 85, SiLU ----
    if (ch < D1) {
        float acc0 = 0.f, acc1 = 0.f, acc2 = 0.f, acc3 = 0.f;
        const float4* W4 = (const float4*)Ws + ch * 27;
        const float4* X4 = (const float4*)B + (qq * 4) * 27;
#pragma unroll 3
        for (int kk = 0; kk < 27; ++kk) {
            float4 w4 = W4[kk];
            float4 a = X4[kk], b = X4[27 + kk], c = X4[54 + kk], d = X4[81 + kk];
            acc0 = fmaf(w4.x, a.x, acc0); acc0 = fmaf(w4.y, a.y, acc0);
            acc0 = fmaf(w4.z, a.z, acc0); acc0 = fmaf(w4.w, a.w, acc0);
            acc1 = fmaf(w4.x, b.x, acc1); acc1 = fmaf(w4.y, b.y, acc1);
            acc1 = fmaf(w4.z, b.z, acc1); acc1 = fmaf(w4.w, b.w, acc1);
            acc2 = fmaf(w4.x, c.x, acc2); acc2 = fmaf(w4.y, c.y, acc2);
            acc2 = fmaf(w4.z, c.z, acc2); acc2 = fmaf(w4.w, c.w, acc2);
            acc3 = fmaf(w4.x, d.x, acc3); acc3 = fmaf(w4.y, d.y, acc3);
            acc3 = fmaf(w4.z, d.z, acc3); acc3 = fmaf(w4.w, d.w, acc3);
        }
        float bias = bd1[ch];
        int nb = qq * 4;
        float z0 = acc0 + bias, z1 = acc1 + bias, z2 = acc2 + bias, z3 = acc3 + bias;
        C[(nb + 0) * 88 + ch] = z0 / (1.f + __expf(-z0));
        C[(nb + 1) * 88 + ch] = z1 / (1.f + __expf(-z1));
        C[(nb + 2) * 88 + ch] = z2 / (1.f + __expf(-z2));
        C[(nb + 3) * 88 + ch] = z3 / (1.f + __expf(-z3));
    } else if (ch < 88) {
        int nb = qq * 4;
#pragma unroll
        for (int n = 0; n < 4; ++n) C[(nb + n) * 88 + ch] = 0.f;
    }
    __syncthreads();

    for (unsigned idx = t; idx < (unsigned)(D2 * 88); idx += 512) {
        unsigned r = idx / 88u, c = idx - r * 88u;
        Ws[r * 92 + c] = (c < D1) ? Wd2[r * D1 + c] : 0.f;
    }
    __syncthreads();

    // ---- L2: 85(->88) -> 64, no activation; Y reuses A ----
    float* Y = A;
    if (ch < D2) {
        float acc0 = 0.f, acc1 = 0.f, acc2 = 0.f, acc3 = 0.f;
        const float4* W4 = (const float4*)Ws + ch * 23;
        const float4* X4 = (const float4*)C + (qq * 4) * 22;
#pragma unroll 2
        for (int kk = 0; kk < 22; ++kk) {
            float4 w4 = W4[kk];
            float4 a = X4[kk], b = X4[22 + kk], c = X4[44 + kk], d = X4[66 + kk];
            acc0 = fmaf(w4.x, a.x, acc0); acc0 = fmaf(w4.y, a.y, acc0);
            acc0 = fmaf(w4.z, a.z, acc0); acc0 = fmaf(w4.w, a.w, acc0);
            acc1 = fmaf(w4.x, b.x, acc1); acc1 = fmaf(w4.y, b.y, acc1);
            acc1 = fmaf(w4.z, b.z, acc1); acc1 = fmaf(w4.w, b.w, acc1);
            acc2 = fmaf(w4.x, c.x, acc2); acc2 = fmaf(w4.y, c.y, acc2);
            acc2 = fmaf(w4.z, c.z, acc2); acc2 = fmaf(w4.w, c.w, acc2);
            acc3 = fmaf(w4.x, d.x, acc3); acc3 = fmaf(w4.y, d.y, acc3);
            acc3 = fmaf(w4.z, d.z, acc3); acc3 = fmaf(w4.w, d.w, acc3);
        }
        float bias = bd2[ch];
        int nb = qq * 4;
        Y[(nb + 0) * 64 + ch] = acc0 + bias;
        Y[(nb + 1) * 64 + ch] = acc1 + bias;
        Y[(nb + 2) * 64 + ch] = acc2 + bias;
        Y[(nb + 3) * 64 + ch] = acc3 + bias;
    }
    __syncthreads();

    // log_softmax over 64: warp w handles node w (16 warps)
    {
        unsigned w = t >> 5, l = t & 31u;
        float v0 = Y[w * 64 + l], v1 = Y[w * 64 + l + 32];
        float m = fmaxf(v0, v1);
        for (int o = 16; o; o >>= 1) m = fmaxf(m, __shfl_xor_sync(~0u, m, o));
        float s = __expf(v0 - m) + __expf(v1 - m);
        for (int o = 16; o; o >>= 1) s += __shfl_xor_sync(~0u, s, o);
        float ls = m + __logf(s);
        int node = base + w;
        out[node * 64 + l]      = v0 - ls;
        out[node * 64 + l + 32] = v1 - ls;
    }
}

// =====================================================================
extern "C" void kernel_launch(void* const* d_in, const int* in_sizes, int n_in,
                              void* d_out, int out_size)
{
    const float* h     = (const float*)d_in[0];
    const float* pos   = (const float*)d_in[1];
    const float* nt    = (const float*)d_in[2];
    const int*   batch = (const int*)  d_in[3];
    const float* Wemb  = (const float*)d_in[4];
    const float* Wqkv  = (const float*)d_in[5];
    const float* bqkv  = (const float*)d_in[6];
    const float* Wb    = (const float*)d_in[7];
    const float* bb    = (const float*)d_in[8];
    const float* Wg    = (const float*)d_in[9];
    const float* bg    = (const float*)d_in[10];
    const float* Wt    = (const float*)d_in[11];
    const float* bt    = (const float*)d_in[12];
    const float* Wd0   = (const float*)d_in[13];
    const float* bd0   = (const float*)d_in[14];
    const float* Wd1   = (const float*)d_in[15];
    const float* bd1   = (const float*)d_in[16];
    const float* Wd2   = (const float*)d_in[17];
    const float* bd2   = (const float*)d_in[18];
    float* out = (float*)d_out;

    const int smem2 = (16 * 132 + 128 * 132) * 4;                      // 76032
    const int smem4 = (16 * 132 + 16 * 108 + 16 * 88 + D0 * 132) * 4;  // 76960
    cudaFuncSetAttribute(k_qkv,   cudaFuncAttributeMaxDynamicSharedMemorySize, smem2);
    cudaFuncSetAttribute(k_dense, cudaFuncAttributeMaxDynamicSharedMemorySize, smem4);

    k_prep <<<NG, 128>>>(nt, Wemb, batch);
    k_qkv  <<<NN / 16, 512, smem2>>>(h, batch, Wqkv, bqkv, Wb, bb, Wg, bg);
    k_attn <<<NG * 2, 512>>>(pos, Wt, bt);
    k_dense<<<NN / 16, 512, smem4>>>(Wd0, bd0, Wd1, bd1, Wd2, bd2, out);
}

// round 13
// speedup vs baseline: 1.9878x; 1.2331x over previous
#include <cuda_runtime.h>
#include <math.h>

// ---------------- problem constants ----------------
#define NG    64      // graphs
#define ATOMS 32      // atoms per graph
#define NN    2048    // total nodes
#define HID   128
#define FEAT  64
#define BINS  32      // dist one-hot bins
#define D0    106     // dense dims: 128 -> 106 -> 85 -> 64
#define D1    85
#define D2    64

typedef unsigned long long u64;

// ---------------- f32x2 packed-math helpers ----------------
__device__ __forceinline__ u64 fma2(u64 a, u64 b, u64 c) {
    u64 d;
    asm("fma.rn.f32x2 %0, %1, %2, %3;" : "=l"(d) : "l"(a), "l"(b), "l"(c));
    return d;
}
__device__ __forceinline__ float fsum2(u64 a) {
    unsigned lo, hi;
    asm("mov.b64 {%0, %1}, %2;" : "=r"(lo), "=r"(hi) : "l"(a));
    return __uint_as_float(lo) + __uint_as_float(hi);
}
__device__ __forceinline__ u64 pack2(float x) {
    u64 d;
    unsigned u = __float_as_uint(x);
    asm("mov.b64 %0, {%1, %1};" : "=l"(d) : "r"(u));
    return d;
}
// ---------------- cp.async helpers ----------------
__device__ __forceinline__ void cp16(unsigned dst, const void* src) {
    asm volatile("cp.async.cg.shared.global [%0], [%1], 16;" :: "r"(dst), "l"(src));
}
#define CP_COMMIT() asm volatile("cp.async.commit_group;")
#define CP_WAIT(n)  asm volatile("cp.async.wait_group %0;" :: "n"(n))

// ---------------- scratch (device globals; no allocs allowed) ----------------
__device__ float g_emb[NG * HID];
__device__ float g_isl[NG];
__device__ float g_x[NN * HID];
__device__ float g_q[NN * HID];
__device__ float g_k[NN * HID];
__device__ float g_v[NN * HID];
__device__ float g_bias[NN];
__device__ float g_gate[NN];
__device__ float g_vals[NN * HID];
// pre-padded dense weights in smem-ready layout (f4 units)
__device__ float4 g_W0p[D0 * 33];   // rows stride 33 f4 (132 f)
__device__ float4 g_W1p[D1 * 27];   // rows stride 27 f4 (108 f), cols>=106 zero
__device__ float4 g_W2p[D2 * 23];   // rows stride 23 f4 (92 f),  cols>=85 zero

// =====================================================================
// Kernel 1: blocks 0..63: emb[g] + lengths. blocks 64..95: pad weights.
// =====================================================================
__global__ __launch_bounds__(128, 1) void k_prep(
    const float* __restrict__ nt, const float* __restrict__ Wemb,
    const int* __restrict__ batch,
    const float* __restrict__ Wd0, const float* __restrict__ Wd1,
    const float* __restrict__ Wd2)
{
    int t = threadIdx.x;
    if (blockIdx.x < NG) {
        __shared__ float4 s_nt[FEAT / 4];
        __shared__ float  s_part[4];
        int g = blockIdx.x;
        if (t < FEAT / 4) s_nt[t] = ((const float4*)(nt + g * FEAT))[t];
        __syncthreads();

        const float4* w4 = (const float4*)Wemb + t * (FEAT / 4);
        float acc = 0.f;
#pragma unroll
        for (int f = 0; f < FEAT / 4; ++f) {
            float4 w = w4[f], x = s_nt[f];
            acc = fmaf(w.x, x.x, acc); acc = fmaf(w.y, x.y, acc);
            acc = fmaf(w.z, x.z, acc); acc = fmaf(w.w, x.w, acc);
        }
        g_emb[g * HID + t] = acc;

        int cnt = 0;
        for (int i = t; i < NN; i += 128) cnt += (batch[i] == g);
        for (int o = 16; o; o >>= 1) cnt += __shfl_down_sync(~0u, cnt, o);
        if ((t & 31) == 0) s_part[t >> 5] = (float)cnt;
        __syncthreads();
        if (t == 0)
            g_isl[g] = rsqrtf(s_part[0] + s_part[1] + s_part[2] + s_part[3]);
    } else {
        const int PT = 32 * 128;
        int pid = (blockIdx.x - NG) * 128 + t;
        for (int i = pid; i < D0 * 33; i += PT) {
            int r = i / 33, c4 = i - r * 33;
            float4 v = make_float4(0.f, 0.f, 0.f, 0.f);
            if (c4 < 32) v = ((const float4*)Wd0)[r * 32 + c4];
            g_W0p[i] = v;
        }
        for (int i = pid; i < D1 * 27; i += PT) {
            int r = i / 27, c = (i - r * 27) * 4;
            const float* row = Wd1 + r * D0;
            float4 v;
            v.x = (c + 0 < D0) ? row[c + 0] : 0.f;
            v.y = (c + 1 < D0) ? row[c + 1] : 0.f;
            v.z = (c + 2 < D0) ? row[c + 2] : 0.f;
            v.w = (c + 3 < D0) ? row[c + 3] : 0.f;
            g_W1p[i] = v;
        }
        for (int i = pid; i < D2 * 23; i += PT) {
            int r = i / 23, c = (i - r * 23) * 4;
            const float* row = Wd2 + r * D1;
            float4 v;
            v.x = (c + 0 < D1) ? row[c + 0] : 0.f;
            v.y = (c + 1 < D1) ? row[c + 1] : 0.f;
            v.z = (c + 2 < D1) ? row[c + 2] : 0.f;
            v.w = (c + 3 < D1) ? row[c + 3] : 0.f;
            g_W2p[i] = v;
        }
    }
}

// =====================================================================
// shared GEMM body: 128-out-ch x 4-node tile, f32x2, k=128 (32 f4)
// =====================================================================
__device__ __forceinline__ void gemm128(
    const float* Wbuf, const float* Xs, unsigned ch, unsigned qq,
    float bias, float* op, int base)
{
    u64 a0 = 0, a1 = 0, a2 = 0, a3 = 0;
    const ulonglong2* W2 = (const ulonglong2*)Wbuf + ch * 33;
    const ulonglong2* X2 = (const ulonglong2*)Xs + (qq * 4) * 33;
#pragma unroll 4
    for (int kk = 0; kk < 32; ++kk) {
        ulonglong2 w = W2[kk];
        ulonglong2 xa = X2[kk], xb = X2[33 + kk], xc = X2[66 + kk], xd = X2[99 + kk];
        a0 = fma2(w.x, xa.x, a0); a0 = fma2(w.y, xa.y, a0);
        a1 = fma2(w.x, xb.x, a1); a1 = fma2(w.y, xb.y, a1);
        a2 = fma2(w.x, xc.x, a2); a2 = fma2(w.y, xc.y, a2);
        a3 = fma2(w.x, xd.x, a3); a3 = fma2(w.y, xd.y, a3);
    }
    int r = base + qq * 4;
    op[(r + 0) * HID + ch] = fsum2(a0) + bias;
    op[(r + 1) * HID + ch] = fsum2(a1) + bias;
    op[(r + 2) * HID + ch] = fsum2(a2) + bias;
    op[(r + 3) * HID + ch] = fsum2(a3) + bias;
}

// =====================================================================
// Kernel 2: x = h*emb[batch]; qkv; bias; gate.
// grid 128 (16 nodes), block 512. Triple-buffered cp.async weights.
// Each weight chunk: 128 rows x 32 f4 = 4096 source f4 (NOT 4224 —
// 4224 is the padded smem footprint; R10's OOB bug).
// =====================================================================
__global__ __launch_bounds__(512, 1) void k_qkv(
    const float* __restrict__ h, const int* __restrict__ batch,
    const float* __restrict__ Wqkv, const float* __restrict__ bqkv,
    const float* __restrict__ Wb, const float* __restrict__ bb,
    const float* __restrict__ Wg, const float* __restrict__ bg)
{
    extern __shared__ float sm[];
    float*  Xs  = sm;                     // 16*132
    float*  Wbuf = sm + 16 * 132;         // 3 x (128*132)
    float4* Xs4 = (float4*)Xs;
    unsigned t = threadIdx.x;
    unsigned ch = t & 127u, qq = t >> 7;
    int base = blockIdx.x * 16;
    unsigned sb = (unsigned)__cvta_generic_to_shared(sm);

    // issue all 3 weight-chunk copies as separate groups
#pragma unroll 1
    for (int j = 0; j < 3; ++j) {
        const float4* Wg4 = (const float4*)(Wqkv + j * HID * HID);
        unsigned wb = sb + (16 * 132 + j * 16896) * 4;
#pragma unroll
        for (int i = 0; i < 8; ++i) {
            unsigned idx = t + i * 512u;               // 0..4095
            cp16(wb + ((idx >> 5) * 33 + (idx & 31u)) * 16, Wg4 + idx);
        }
        CP_COMMIT();
    }

    // build x (overlaps weight copies)
    {
        unsigned n = t >> 5, c4 = t & 31u;
        int node = base + n;
        float4 hv = ((const float4*)(h + node * HID))[c4];
        float4 ev = ((const float4*)(g_emb + batch[node] * HID))[c4];
        float4 xv = make_float4(hv.x * ev.x, hv.y * ev.y, hv.z * ev.z, hv.w * ev.w);
        Xs4[n * 33 + c4] = xv;
        ((float4*)(g_x + node * HID))[c4] = xv;
    }
    __syncthreads();

    // bias & gate (overlaps weight copies): warp w handles node w
    {
        unsigned w = t >> 5, l = t & 31u;
        float pb = 0.f, pg = 0.f;
#pragma unroll
        for (int m = 0; m < 4; ++m) {
            float xv = Xs[w * 132 + l + 32 * m];
            pb = fmaf(xv, Wb[l + 32 * m], pb);
            pg = fmaf(xv, Wg[l + 32 * m], pg);
        }
        for (int o = 16; o; o >>= 1) {
            pb += __shfl_down_sync(~0u, pb, o);
            pg += __shfl_down_sync(~0u, pg, o);
        }
        if (l == 0) {
            g_bias[base + w] = pb + bb[0];
            float z = pg + bg[0];
            g_gate[base + w] = 1.f / (1.f + __expf(-z));
        }
    }

    CP_WAIT(2); __syncthreads();
    gemm128(Wbuf, Xs, ch, qq, bqkv[ch], g_q, base);
    CP_WAIT(1); __syncthreads();
    gemm128(Wbuf + 16896, Xs, ch, qq, bqkv[HID + ch], g_k, base);
    CP_WAIT(0); __syncthreads();
    gemm128(Wbuf + 2 * 16896, Xs, ch, qq, bqkv[2 * HID + ch], g_v, base);
}

// =====================================================================
// Kernel 3: block-diagonal attention. grid 128, block 512.
// =====================================================================
__global__ __launch_bounds__(512, 1) void k_attn(
    const float* __restrict__ pos, const float* __restrict__ Wt,
    const float* __restrict__ bt)
{
    __shared__ float Qs[16 * 132];
    __shared__ float Ks[32 * 132];
    __shared__ float Vs[32 * 132];
    __shared__ float Ls[16 * 33];
    __shared__ float4 posS[32];
    __shared__ float biasS[16], gateS[16], WtS[32];

    unsigned t = threadIdx.x;
    int g = blockIdx.x >> 1;
    int half = blockIdx.x & 1;
    int row0 = g * ATOMS + half * 16;
    int col0 = g * ATOMS;

    unsigned sbQ = (unsigned)__cvta_generic_to_shared(Qs);
    unsigned sbK = (unsigned)__cvta_generic_to_shared(Ks);
    unsigned sbV = (unsigned)__cvta_generic_to_shared(Vs);

    // stage Q/K/V via cp.async (overlaps the scalar staging below)
    {
        unsigned n = t >> 5, c4 = t & 31u;
        cp16(sbQ + (n * 33 + c4) * 16, ((const float4*)(g_q + (row0 + n) * HID)) + c4);
#pragma unroll
        for (int i = 0; i < 2; ++i) {
            unsigned idx = t + i * 512u;
            unsigned kn = idx >> 5, kc = idx & 31u;
            cp16(sbK + (kn * 33 + kc) * 16, ((const float4*)(g_k + (col0 + kn) * HID)) + kc);
            cp16(sbV + (kn * 33 + kc) * 16, ((const float4*)(g_v + (col0 + kn) * HID)) + kc);
        }
        CP_COMMIT();
    }
    if (t < 32) {
        posS[t] = make_float4(pos[(col0 + t) * 3], pos[(col0 + t) * 3 + 1],
                              pos[(col0 + t) * 3 + 2], 0.f);
        WtS[t] = Wt[t];
    }
    if (t < 16) { biasS[t] = g_bias[row0 + t]; gateS[t] = g_gate[row0 + t]; }
    CP_WAIT(0);
    __syncthreads();

    float isl = g_isl[g];
    float btv = bt[0];

    // logits: one (i,j) pair per thread
    {
        unsigned i = t >> 5, j = t & 31u;
        const ulonglong2* Q2 = (const ulonglong2*)Qs + i * 33;
        const ulonglong2* K2 = (const ulonglong2*)Ks + j * 33;
        u64 acc = 0;
#pragma unroll 8
        for (int kk = 0; kk < 32; ++kk) {
            ulonglong2 q2 = Q2[kk], k2 = K2[kk];
            acc = fma2(q2.x, k2.x, acc);
            acc = fma2(q2.y, k2.y, acc);
        }
        float qk = fsum2(acc);
        float4 pi = posS[half * 16 + i];
        float4 pj = posS[j];
        float dx = pi.x - pj.x, dy = pi.y - pj.y, dz = pi.z - pj.z;
        float d = sqrtf(fmaxf(dx * dx + dy * dy + dz * dz, 1e-12f));
        // windowed SoftOneHot: bins beyond +-5 steps contribute < 5e-12
        const float step = 10.f / 31.f;
        int m0 = (int)(d * (31.f / 10.f)) - 4;
        m0 = max(0, min(BINS - 10, m0));
        float tv = btv;
#pragma unroll
        for (int m = 0; m < 10; ++m) {
            float c = step * (float)(m0 + m);
            float df = d - c;
            tv = fmaf(__expf(-10.f * df * df), WtS[m0 + m], tv);
        }
        Ls[i * 33 + j] = qk * isl + biasS[i] + tv;
    }
    __syncthreads();

    // softmax: warp w handles row w
    {
        unsigned w = t >> 5, l = t & 31u;
        float v = Ls[w * 33 + l];
        float m = v;
        for (int o = 16; o; o >>= 1) m = fmaxf(m, __shfl_xor_sync(~0u, m, o));
        float e = __expf(v - m);
        float s = e;
        for (int o = 16; o; o >>= 1) s += __shfl_xor_sync(~0u, s, o);
        Ls[w * 33 + l] = e / s;
    }
    __syncthreads();

    // attn@v + gate + residual
    {
        unsigned w = t >> 5, lane = t & 31u;
        u64 acc01 = 0, acc23 = 0;
        const ulonglong2* V2 = (const ulonglong2*)Vs;
#pragma unroll 8
        for (int j = 0; j < 32; ++j) {
            u64 aa = pack2(Ls[w * 33 + j]);
            ulonglong2 v2 = V2[j * 33 + lane];
            acc01 = fma2(aa, v2.x, acc01);
            acc23 = fma2(aa, v2.y, acc23);
        }
        int node = row0 + w;
        u64 gg = pack2(gateS[w]);
        ulonglong2 x2 = ((const ulonglong2*)(g_x + node * HID))[lane];
        ulonglong2 o2;
        o2.x = fma2(acc01, gg, x2.x);
        o2.y = fma2(acc23, gg, x2.y);
        ((ulonglong2*)(g_vals + node * HID))[lane] = o2;
    }
}

// =====================================================================
// Kernel 4: dense head 128->106->85->64 + log_softmax.
// grid 128 (16 nodes), block 512. All weight staging via cp.async
// groups issued up-front; W1/W2 hidden under L0/L1 compute.
// =====================================================================
__global__ __launch_bounds__(512, 1) void k_dense(
    const float* __restrict__ bd0, const float* __restrict__ bd1,
    const float* __restrict__ bd2, float* __restrict__ out)
{
    extern __shared__ float sm[];
    float* A   = sm;                      // 16*132  (vals, reused for Y)
    float* B   = A + 16 * 132;            // 16*108
    float* C   = B + 16 * 108;            // 16*88
    float* W0s = C + 16 * 88;             // 106*132
    float* W1s = W0s + D0 * 132;          // 85*108
    float* W2s = W1s + D1 * 108;          // 64*92
    unsigned t = threadIdx.x;
    unsigned ch = t & 127u, qq = t >> 7;
    int base = blockIdx.x * 16;
    unsigned sb = (unsigned)__cvta_generic_to_shared(sm);
    const unsigned offA  = 0;
    const unsigned offW0 = (unsigned)((16 * 132 + 16 * 108 + 16 * 88) * 4);
    const unsigned offW1 = offW0 + (unsigned)(D0 * 132 * 4);
    const unsigned offW2 = offW1 + (unsigned)(D1 * 108 * 4);

    // group0: A + W0
    {
        unsigned n = t >> 5, c4 = t & 31u;
        cp16(sb + offA + (n * 33 + c4) * 16,
             ((const float4*)(g_vals + (base + n) * HID)) + c4);
    }
#pragma unroll
    for (int i = 0; i < 7; ++i) {
        unsigned idx = t + i * 512u;
        if (idx < (unsigned)(D0 * 33)) cp16(sb + offW0 + idx * 16, g_W0p + idx);
    }
    CP_COMMIT();
    // group1: W1
#pragma unroll
    for (int i = 0; i < 5; ++i) {
        unsigned idx = t + i * 512u;
        if (idx < (unsigned)(D1 * 27)) cp16(sb + offW1 + idx * 16, g_W1p + idx);
    }
    CP_COMMIT();
    // group2: W2
#pragma unroll
    for (int i = 0; i < 3; ++i) {
        unsigned idx = t + i * 512u;
        if (idx < (unsigned)(D2 * 23)) cp16(sb + offW2 + idx * 16, g_W2p + idx);
    }
    CP_COMMIT();

    CP_WAIT(2); __syncthreads();

    // ---- L0: 128 -> 106, SiLU ----
    if (ch < D0) {
        u64 a0 = 0, a1 = 0, a2 = 0, a3 = 0;
        const ulonglong2* W2p = (const ulonglong2*)W0s + ch * 33;
        const ulonglong2* X2p = (const ulonglong2*)A + (qq * 4) * 33;
#pragma unroll 4
        for (int kk = 0; kk < 32; ++kk) {
            ulonglong2 w = W2p[kk];
            ulonglong2 xa = X2p[kk], xb = X2p[33 + kk], xc = X2p[66 + kk], xd = X2p[99 + kk];
            a0 = fma2(w.x, xa.x, a0); a0 = fma2(w.y, xa.y, a0);
            a1 = fma2(w.x, xb.x, a1); a1 = fma2(w.y, xb.y, a1);
            a2 = fma2(w.x, xc.x, a2); a2 = fma2(w.y, xc.y, a2);
            a3 = fma2(w.x, xd.x, a3); a3 = fma2(w.y, xd.y, a3);
        }
        float bias = bd0[ch];
        int nb = qq * 4;
        float z0 = fsum2(a0) + bias, z1 = fsum2(a1) + bias;
        float z2 = fsum2(a2) + bias, z3 = fsum2(a3) + bias;
        B[(nb + 0) * 108 + ch] = z0 / (1.f + __expf(-z0));
        B[(nb + 1) * 108 + ch] = z1 / (1.f + __expf(-z1));
        B[(nb + 2) * 108 + ch] = z2 / (1.f + __expf(-z2));
        B[(nb + 3) * 108 + ch] = z3 / (1.f + __expf(-z3));
    } else if (ch < 108) {
        int nb = qq * 4;
#pragma unroll
        for (int n = 0; n < 4; ++n) B[(nb + n) * 108 + ch] = 0.f;
    }
    CP_WAIT(1); __syncthreads();

    // ---- L1: 106(->108) -> 85, SiLU ----
    if (ch < D1) {
        u64 a0 = 0, a1 = 0, a2 = 0, a3 = 0;
        const ulonglong2* W2p = (const ulonglong2*)W1s + ch * 27;
        const ulonglong2* X2p = (const ulonglong2*)B + (qq * 4) * 27;
#pragma unroll 3
        for (int kk = 0; kk < 27; ++kk) {
            ulonglong2 w = W2p[kk];
            ulonglong2 xa = X2p[kk], xb = X2p[27 + kk], xc = X2p[54 + kk], xd = X2p[81 + kk];
            a0 = fma2(w.x, xa.x, a0); a0 = fma2(w.y, xa.y, a0);
            a1 = fma2(w.x, xb.x, a1); a1 = fma2(w.y, xb.y, a1);
            a2 = fma2(w.x, xc.x, a2); a2 = fma2(w.y, xc.y, a2);
            a3 = fma2(w.x, xd.x, a3); a3 = fma2(w.y, xd.y, a3);
        }
        float bias = bd1[ch];
        int nb = qq * 4;
        float z0 = fsum2(a0) + bias, z1 = fsum2(a1) + bias;
        float z2 = fsum2(a2) + bias, z3 = fsum2(a3) + bias;
        C[(nb + 0) * 88 + ch] = z0 / (1.f + __expf(-z0));
        C[(nb + 1) * 88 + ch] = z1 / (1.f + __expf(-z1));
        C[(nb + 2) * 88 + ch] = z2 / (1.f + __expf(-z2));
        C[(nb + 3) * 88 + ch] = z3 / (1.f + __expf(-z3));
    } else if (ch < 88) {
        int nb = qq * 4;
#pragma unroll
        for (int n = 0; n < 4; ++n) C[(nb + n) * 88 + ch] = 0.f;
    }
    CP_WAIT(0); __syncthreads();

    // ---- L2: 85(->88) -> 64, no activation; Y reuses A ----
    float* Y = A;
    if (ch < D2) {
        u64 a0 = 0, a1 = 0, a2 = 0, a3 = 0;
        const ulonglong2* W2p = (const ulonglong2*)W2s + ch * 23;
        const ulonglong2* X2p = (const ulonglong2*)C + (qq * 4) * 22;
#pragma unroll 2
        for (int kk = 0; kk < 22; ++kk) {
            ulonglong2 w = W2p[kk];
            ulonglong2 xa = X2p[kk], xb = X2p[22 + kk], xc = X2p[44 + kk], xd = X2p[66 + kk];
            a0 = fma2(w.x, xa.x, a0); a0 = fma2(w.y, xa.y, a0);
            a1 = fma2(w.x, xb.x, a1); a1 = fma2(w.y, xb.y, a1);
            a2 = fma2(w.x, xc.x, a2); a2 = fma2(w.y, xc.y, a2);
            a3 = fma2(w.x, xd.x, a3); a3 = fma2(w.y, xd.y, a3);
        }
        float bias = bd2[ch];
        int nb = qq * 4;
        Y[(nb + 0) * 64 + ch] = fsum2(a0) + bias;
        Y[(nb + 1) * 64 + ch] = fsum2(a1) + bias;
        Y[(nb + 2) * 64 + ch] = fsum2(a2) + bias;
        Y[(nb + 3) * 64 + ch] = fsum2(a3) + bias;
    }
    __syncthreads();

    // log_softmax over 64: warp w handles node w
    {
        unsigned w = t >> 5, l = t & 31u;
        float v0 = Y[w * 64 + l], v1 = Y[w * 64 + l + 32];
        float m = fmaxf(v0, v1);
        for (int o = 16; o; o >>= 1) m = fmaxf(m, __shfl_xor_sync(~0u, m, o));
        float s = __expf(v0 - m) + __expf(v1 - m);
        for (int o = 16; o; o >>= 1) s += __shfl_xor_sync(~0u, s, o);
        float ls = m + __logf(s);
        int node = base + w;
        out[node * 64 + l]      = v0 - ls;
        out[node * 64 + l + 32] = v1 - ls;
    }
}

// =====================================================================
extern "C" void kernel_launch(void* const* d_in, const int* in_sizes, int n_in,
                              void* d_out, int out_size)
{
    const float* h     = (const float*)d_in[0];
    const float* pos   = (const float*)d_in[1];
    const float* nt    = (const float*)d_in[2];
    const int*   batch = (const int*)  d_in[3];
    const float* Wemb  = (const float*)d_in[4];
    const float* Wqkv  = (const float*)d_in[5];
    const float* bqkv  = (const float*)d_in[6];
    const float* Wb    = (const float*)d_in[7];
    const float* bb    = (const float*)d_in[8];
    const float* Wg    = (const float*)d_in[9];
    const float* bg    = (const float*)d_in[10];
    const float* Wt    = (const float*)d_in[11];
    const float* bt    = (const float*)d_in[12];
    const float* Wd0   = (const float*)d_in[13];
    const float* bd0   = (const float*)d_in[14];
    const float* Wd1   = (const float*)d_in[15];
    const float* bd1   = (const float*)d_in[16];
    const float* Wd2   = (const float*)d_in[17];
    const float* bd2   = (const float*)d_in[18];
    float* out = (float*)d_out;

    const int smem2 = (16 * 132 + 3 * 128 * 132) * 4;                        // 211200
    const int smem4 = (16 * 132 + 16 * 108 + 16 * 88 +
                       D0 * 132 + D1 * 108 + D2 * 92) * 4;                   // 137232
    cudaFuncSetAttribute(k_qkv,   cudaFuncAttributeMaxDynamicSharedMemorySize, smem2);
    cudaFuncSetAttribute(k_dense, cudaFuncAttributeMaxDynamicSharedMemorySize, smem4);

    k_prep <<<NG + 32, 128>>>(nt, Wemb, batch, Wd0, Wd1, Wd2);
    k_qkv  <<<NN / 16, 512, smem2>>>(h, batch, Wqkv, bqkv, Wb, bb, Wg, bg);
    k_attn <<<NG * 2, 512>>>(pos, Wt, bt);
    k_dense<<<NN / 16, 512, smem4>>>(bd0, bd1, bd2, out);
}